// round 15
// baseline (speedup 1.0000x reference)
#include <cuda_runtime.h>
#include <math.h>

#define NNODES 50000
#define LDIM   4
#define DDIM   128
#define KDIM   16
#define EEDGES 800000
#define MROWS  (LDIM * NNODES)        // 200000, multiple of 64
#define DECAYF 0.7f
#define EPSF   1e-5f

// ---------------- scratch (device globals; no allocation) ----------------
__device__ float g_v   [MROWS * DDIM];
__device__ float g_agg [MROWS * DDIM];
__device__ float g_sage[MROWS * DDIM];
__device__ float g_w0 [MROWS];
__device__ float g_it1[MROWS];
__device__ float g_it2[MROWS];

// CSR build scratch (cnt and cur share one buffer -> one memset)
__device__ int   g_cnt2[2 * NNODES];
__device__ int   g_rowstart[NNODES + 1];
__device__ int   g_ecol[EEDGES];
__device__ float g_eval[EEDGES];

__device__ __forceinline__ unsigned f2tf(float f)
{
    unsigned u;
    asm("cvt.rna.tf32.f32 %0, %1;" : "=r"(u) : "f"(f));
    return u;
}

// ================= CSR construction =================
__global__ void hist_kernel(const int* __restrict__ ei, int* __restrict__ cnt)
{
    int e = blockIdx.x * blockDim.x + threadIdx.x;
    if (e < EEDGES) atomicAdd(&cnt[ei[e]], 1);
}

__global__ void scan_kernel(const int* __restrict__ cnt, int* __restrict__ rowstart)
{
    const int T = 1024;
    __shared__ int partial[T];
    const int tid = threadIdx.x;
    const int chunk = (NNODES + T - 1) / T;
    const int base = tid * chunk;
    int s = 0;
    for (int i = 0; i < chunk; i++) {
        int idx = base + i;
        if (idx < NNODES) s += cnt[idx];
    }
    partial[tid] = s;
    __syncthreads();
    for (int off = 1; off < T; off <<= 1) {
        int v = (tid >= off) ? partial[tid - off] : 0;
        __syncthreads();
        partial[tid] += v;
        __syncthreads();
    }
    int run = (tid == 0) ? 0 : partial[tid - 1];
    for (int i = 0; i < chunk; i++) {
        int idx = base + i;
        if (idx < NNODES) { rowstart[idx] = run; run += cnt[idx]; }
    }
    if (tid == T - 1) rowstart[NNODES] = run;
}

__global__ void scatter_kernel(const int* __restrict__ ei, const float* __restrict__ ev,
                               const int* __restrict__ rowstart, int* __restrict__ cur,
                               int* __restrict__ ecol, float* __restrict__ eval_)
{
    int e = blockIdx.x * blockDim.x + threadIdx.x;
    if (e >= EEDGES) return;
    const int r = ei[e];
    const int pos = rowstart[r] + atomicAdd(&cur[r], 1);
    ecol[pos]  = ei[EEDGES + e];
    eval_[pos] = ev[e];
}

// ================= gather spmm: merged, blockIdx.y = l (slice-major order) ===
__global__ void __launch_bounds__(256) spmm_all(
    const int* __restrict__ rowstart,
    const int* __restrict__ ecol, const float* __restrict__ eval_,
    const float* __restrict__ x, float* __restrict__ agg)
{
    const int l = blockIdx.y;
    const int row = (blockIdx.x * blockDim.x + threadIdx.x) >> 5;
    const int lane = threadIdx.x & 31;
    if (row >= NNODES) return;

    const int s = rowstart[row];
    const int e = rowstart[row + 1];
    const float4* xl = (const float4*)x + (size_t)l * NNODES * 32;

    float4 acc = make_float4(0.f, 0.f, 0.f, 0.f);
    int i = s;
    for (; i + 4 <= e; i += 4) {
        const int   c0 = ecol[i],   c1 = ecol[i+1], c2 = ecol[i+2], c3 = ecol[i+3];
        const float v0 = eval_[i],  v1 = eval_[i+1], v2 = eval_[i+2], v3 = eval_[i+3];
        float4 x0 = xl[(size_t)c0 * 32 + lane];
        float4 x1 = xl[(size_t)c1 * 32 + lane];
        float4 x2 = xl[(size_t)c2 * 32 + lane];
        float4 x3 = xl[(size_t)c3 * 32 + lane];
        acc.x += v0 * x0.x; acc.y += v0 * x0.y; acc.z += v0 * x0.z; acc.w += v0 * x0.w;
        acc.x += v1 * x1.x; acc.y += v1 * x1.y; acc.z += v1 * x1.z; acc.w += v1 * x1.w;
        acc.x += v2 * x2.x; acc.y += v2 * x2.y; acc.z += v2 * x2.z; acc.w += v2 * x2.w;
        acc.x += v3 * x3.x; acc.y += v3 * x3.y; acc.z += v3 * x3.z; acc.w += v3 * x3.w;
    }
    for (; i < e; i++) {
        const int c0 = ecol[i];
        const float v0 = eval_[i];
        float4 x0 = xl[(size_t)c0 * 32 + lane];
        acc.x += v0 * x0.x; acc.y += v0 * x0.y; acc.z += v0 * x0.z; acc.w += v0 * x0.w;
    }
    ((float4*)agg)[((size_t)l * NNODES + row) * 32 + lane] = acc;
}

// ================= retention spmm on [L,N] weights (gather) =================
__global__ void __launch_bounds__(256) ret_gather(
    const int* __restrict__ rowstart,
    const int* __restrict__ ecol, const float* __restrict__ eval_,
    const float* __restrict__ src, float* __restrict__ dst)
{
    const int row = (blockIdx.x * blockDim.x + threadIdx.x) >> 5;
    const int lane = threadIdx.x & 31;
    if (row >= NNODES) return;
    const int s = rowstart[row];
    const int e = rowstart[row + 1];

    float a0 = 0.f, a1 = 0.f, a2 = 0.f, a3 = 0.f;
    for (int i = s + lane; i < e; i += 32) {
        const int c = ecol[i];
        const float v = DECAYF * eval_[i];
        a0 += v * src[c];
        a1 += v * src[NNODES + c];
        a2 += v * src[2 * NNODES + c];
        a3 += v * src[3 * NNODES + c];
    }
#pragma unroll
    for (int off = 16; off; off >>= 1) {
        a0 += __shfl_xor_sync(0xFFFFFFFFu, a0, off);
        a1 += __shfl_xor_sync(0xFFFFFFFFu, a1, off);
        a2 += __shfl_xor_sync(0xFFFFFFFFu, a2, off);
        a3 += __shfl_xor_sync(0xFFFFFFFFu, a3, off);
    }
    if (lane == 0) {
        dst[row]              = a0;
        dst[NNODES + row]     = a1;
        dst[2 * NNODES + row] = a2;
        dst[3 * NNODES + row] = a3;
    }
}

// ================= common MMA helpers =================
#define AST 132
#define BST 132
#define GEMM_SMEM ((64 * AST + 128 * BST) * 4)   // 101376 bytes

__device__ __forceinline__ void mma8(float* c, const unsigned* a, unsigned b0, unsigned b1)
{
    asm volatile(
        "mma.sync.aligned.m16n8k8.row.col.f32.tf32.tf32.f32 "
        "{%0,%1,%2,%3},{%4,%5,%6,%7},{%8,%9},{%0,%1,%2,%3};"
        : "+f"(c[0]), "+f"(c[1]), "+f"(c[2]), "+f"(c[3])
        : "r"(a[0]), "r"(a[1]), "r"(a[2]), "r"(a[3]), "r"(b0), "r"(b1));
}

#define LDSM4(r, addr) \
    asm volatile("ldmatrix.sync.aligned.m8n8.x4.shared.b16 {%0,%1,%2,%3}, [%4];" \
        : "=r"((r)[0]), "=r"((r)[1]), "=r"((r)[2]), "=r"((r)[3]) : "r"(addr))

__device__ __forceinline__ void fillA(unsigned* As, const float* A, int blockRow, int tid)
{
    const float4* Ag = (const float4*)(A + (size_t)blockRow * DDIM);
#pragma unroll
    for (int f = 0; f < 8; f++) {
        int i4 = tid + f * 256;
        float4 t = Ag[i4];
        int e = i4 * 4;
        *(uint4*)(As + (e >> 7) * AST + (e & 127)) =
            make_uint4(f2tf(t.x), f2tf(t.y), f2tf(t.z), f2tf(t.w));
    }
}

// B-tile fill with in-kernel transpose+convert: Bs[n][k] = tf32(W[k*128+n]).
// Per-(n,kq) uint4 store: lane n covers banks 4n..4n+3 mod 32 -> conflict-free.
// Global loads per j are coalesced 128B segments; W stays L1-resident.
__device__ __forceinline__ void fillB_t(unsigned* Bs, const float* W, int tid)
{
#pragma unroll
    for (int f = 0; f < 16; f++) {
        int idx = f * 256 + tid;          // 0..4095
        int n  = idx & 127;
        int kq = idx >> 7;                // 0..31
        float a = W[(4 * kq + 0) * DDIM + n];
        float b = W[(4 * kq + 1) * DDIM + n];
        float c = W[(4 * kq + 2) * DDIM + n];
        float d = W[(4 * kq + 3) * DDIM + n];
        *(uint4*)(Bs + n * BST + 4 * kq) =
            make_uint4(f2tf(a), f2tf(b), f2tf(c), f2tf(d));
    }
}

__device__ __forceinline__ void mma_loop(float acc[8][4], unsigned aAddr, unsigned bAddr)
{
#pragma unroll
    for (int k8 = 0; k8 < 16; k8++) {
        const unsigned ko = k8 * 32;
        unsigned af[4], bf[4][4];
        LDSM4(af, aAddr + ko);
        LDSM4(bf[0], bAddr + ko);
        LDSM4(bf[1], bAddr + 16 * BST * 4 + ko);
        LDSM4(bf[2], bAddr + 32 * BST * 4 + ko);
        LDSM4(bf[3], bAddr + 48 * BST * 4 + ko);
#pragma unroll
        for (int nt = 0; nt < 8; nt++)
            mma8(acc[nt], af, bf[nt >> 1][(nt & 1) * 2], bf[nt >> 1][(nt & 1) * 2 + 1]);
    }
}

// LN(silu(.)) -> global store
__device__ __forceinline__ void ln_epilogue(
    const float* Cs, int blockRow, int wid, int lane,
    const float* bias, const float* addb,
    const float* lng, const float* lnb, float* C)
{
    float4 bias4 = make_float4(0.f, 0.f, 0.f, 0.f);
    if (bias) bias4 = ((const float4*)bias)[lane];
    const float4 g4 = ((const float4*)lng)[lane];
    const float4 b4 = ((const float4*)lnb)[lane];
#pragma unroll
    for (int i = 0; i < 8; i++) {
        const int r = wid * 8 + i;
        const size_t gr_ = (size_t)blockRow + r;
        float4 t = *(const float4*)(Cs + r * AST + lane * 4);
        t.x += bias4.x; t.y += bias4.y; t.z += bias4.z; t.w += bias4.w;
        if (addb) {
            float4 ad = ((const float4*)addb)[gr_ * 32 + lane];
            t.x += ad.x; t.y += ad.y; t.z += ad.z; t.w += ad.w;
        }
        float4 s;
        s.x = t.x / (1.f + expf(-t.x));
        s.y = t.y / (1.f + expf(-t.y));
        s.z = t.z / (1.f + expf(-t.z));
        s.w = t.w / (1.f + expf(-t.w));
        float sum = s.x + s.y + s.z + s.w;
        float sq  = s.x * s.x + s.y * s.y + s.z * s.z + s.w * s.w;
#pragma unroll
        for (int off = 16; off; off >>= 1) {
            sum += __shfl_xor_sync(0xFFFFFFFFu, sum, off);
            sq  += __shfl_xor_sync(0xFFFFFFFFu, sq,  off);
        }
        const float mean = sum * (1.f / 128.f);
        const float var  = sq * (1.f / 128.f) - mean * mean;
        const float rstd = rsqrtf(var + EPSF);
        float4 o;
        o.x = (s.x - mean) * rstd * g4.x + b4.x;
        o.y = (s.y - mean) * rstd * g4.y + b4.y;
        o.z = (s.z - mean) * rstd * g4.z + b4.z;
        o.w = (s.w - mean) * rstd * g4.w + b4.w;
        ((float4*)C)[gr_ * 32 + lane] = o;
    }
}

// LN(silu(.)) -> tf32 into As tile (for chained GEMM)
__device__ __forceinline__ void ln_to_As(
    const float* CsB, unsigned* As, int wid, int lane,
    const float* bias, const float* lng, const float* lnb)
{
    float4 bias4 = make_float4(0.f, 0.f, 0.f, 0.f);
    if (bias) bias4 = ((const float4*)bias)[lane];
    const float4 g4 = ((const float4*)lng)[lane];
    const float4 b4 = ((const float4*)lnb)[lane];
#pragma unroll
    for (int i = 0; i < 8; i++) {
        const int r = wid * 8 + i;
        float4 t = *(const float4*)(CsB + r * AST + lane * 4);
        t.x += bias4.x; t.y += bias4.y; t.z += bias4.z; t.w += bias4.w;
        float4 s;
        s.x = t.x / (1.f + expf(-t.x));
        s.y = t.y / (1.f + expf(-t.y));
        s.z = t.z / (1.f + expf(-t.z));
        s.w = t.w / (1.f + expf(-t.w));
        float sum = s.x + s.y + s.z + s.w;
        float sq  = s.x * s.x + s.y * s.y + s.z * s.z + s.w * s.w;
#pragma unroll
        for (int off = 16; off; off >>= 1) {
            sum += __shfl_xor_sync(0xFFFFFFFFu, sum, off);
            sq  += __shfl_xor_sync(0xFFFFFFFFu, sq,  off);
        }
        const float mean = sum * (1.f / 128.f);
        const float var  = sq * (1.f / 128.f) - mean * mean;
        const float rstd = rsqrtf(var + EPSF);
        float4 o;
        o.x = (s.x - mean) * rstd * g4.x + b4.x;
        o.y = (s.y - mean) * rstd * g4.y + b4.y;
        o.z = (s.z - mean) * rstd * g4.z + b4.z;
        o.w = (s.w - mean) * rstd * g4.w + b4.w;
        *(uint4*)(As + r * AST + lane * 4) =
            make_uint4(f2tf(o.x), f2tf(o.y), f2tf(o.z), f2tf(o.w));
    }
}

__device__ __forceinline__ void stage_acc(float* Cs, const float acc[8][4],
                                          int wr, int wc, int tg, int gr)
{
    const int r0 = wr * 16 + gr;
#pragma unroll
    for (int nt = 0; nt < 8; nt++) {
        const int c = wc * 64 + nt * 8 + 2 * tg;
        *(float2*)(Cs + r0 * AST + c)       = make_float2(acc[nt][0], acc[nt][1]);
        *(float2*)(Cs + (r0 + 8) * AST + c) = make_float2(acc[nt][2], acc[nt][3]);
    }
}

// ================= fused_front: v = x@Wv ; sage = LN(silu(x@W + b + agg@aggW)) =
__global__ void __launch_bounds__(256, 2) fused_front(
    const float* __restrict__ x, const float* __restrict__ agg,
    const float* __restrict__ sage_W, const float* __restrict__ att_Wv,
    const float* __restrict__ sage_aggW,
    const float* __restrict__ sage_b,
    const float* __restrict__ lng, const float* __restrict__ lnb,
    float* __restrict__ v, float* __restrict__ sage)
{
    extern __shared__ unsigned smem_u[];
    unsigned* As = smem_u;
    unsigned* Bs = smem_u + 64 * AST;
    float* Cs = (float*)smem_u;

    const int tid  = threadIdx.x;
    const int lane = tid & 31;
    const int wid  = tid >> 5;
    const int wr   = wid & 3;
    const int wc   = wid >> 2;
    const int tg   = lane & 3;
    const int gr   = lane >> 2;
    const int blockRow = blockIdx.x * 64;

    const unsigned sbase = (unsigned)__cvta_generic_to_shared(smem_u);
    const unsigned aAddr = sbase +
        ((wr * 16 + (lane & 15)) * AST + (lane >> 4) * 4) * 4u;
    const unsigned bAddr = sbase + 64u * AST * 4u +
        ((wc * 64 + (lane >> 4) * 8 + (lane & 7)) * BST + ((lane >> 3) & 1) * 4) * 4u;

    float acc[8][4];

    // pass 1: v = x @ Wv
    fillA(As, x, blockRow, tid);
    fillB_t(Bs, att_Wv, tid);
    __syncthreads();
#pragma unroll
    for (int i = 0; i < 8; i++)
#pragma unroll
        for (int j = 0; j < 4; j++) acc[i][j] = 0.f;
    mma_loop(acc, aAddr, bAddr);
    {
        const int r0 = blockRow + wr * 16 + gr;
#pragma unroll
        for (int nt = 0; nt < 8; nt++) {
            const int c = wc * 64 + nt * 8 + 2 * tg;
            ((float2*)v)[(size_t)r0 * 64 + (c >> 1)]       = make_float2(acc[nt][0], acc[nt][1]);
            ((float2*)v)[(size_t)(r0 + 8) * 64 + (c >> 1)] = make_float2(acc[nt][2], acc[nt][3]);
        }
    }
    __syncthreads();

    // pass 2: acc = x @ sage_W   (As still holds x)
    fillB_t(Bs, sage_W, tid);
    __syncthreads();
#pragma unroll
    for (int i = 0; i < 8; i++)
#pragma unroll
        for (int j = 0; j < 4; j++) acc[i][j] = 0.f;
    mma_loop(acc, aAddr, bAddr);
    __syncthreads();

    // pass 3: acc += agg @ aggW
    fillA(As, agg, blockRow, tid);
    fillB_t(Bs, sage_aggW, tid);
    __syncthreads();
    mma_loop(acc, aAddr, bAddr);
    __syncthreads();

    stage_acc(Cs, acc, wr, wc, tg, gr);
    __syncthreads();
    ln_epilogue(Cs, blockRow, wid, lane, sage_b, nullptr, lng, lnb, sage);
}

// ================= gemm_back: lin1 (+att on the fly) chained into lin2 =======
__global__ void __launch_bounds__(256, 2) gemm_back(
    const float* __restrict__ sage, const float* __restrict__ v,
    const float* __restrict__ w0, const float* __restrict__ it1,
    const float* __restrict__ it2,
    const float* __restrict__ attg, const float* __restrict__ attb,
    const float* __restrict__ lin1_W, const float* __restrict__ lin1_b,
    const float* __restrict__ ln1g, const float* __restrict__ ln1b,
    const float* __restrict__ lin2_W, const float* __restrict__ lin2_b,
    const float* __restrict__ x,
    const float* __restrict__ ln2g, const float* __restrict__ ln2b,
    float* __restrict__ out)
{
    extern __shared__ unsigned smem_u[];
    unsigned* As = smem_u;
    unsigned* Bs = smem_u + 64 * AST;
    float* CsA = (float*)smem_u;
    float* CsB = (float*)(smem_u + 64 * AST);

    const int tid  = threadIdx.x;
    const int lane = tid & 31;
    const int wid  = tid >> 5;
    const int wr   = wid & 3;
    const int wc   = wid >> 2;
    const int tg   = lane & 3;
    const int gr   = lane >> 2;
    const int blockRow = blockIdx.x * 64;

    const unsigned sbase = (unsigned)__cvta_generic_to_shared(smem_u);
    const unsigned aAddr = sbase +
        ((wr * 16 + (lane & 15)) * AST + (lane >> 4) * 4) * 4u;
    const unsigned bAddr = sbase + 64u * AST * 4u +
        ((wc * 64 + (lane >> 4) * 8 + (lane & 7)) * BST + ((lane >> 3) & 1) * 4) * 4u;

    float acc[8][4];
#pragma unroll
    for (int i = 0; i < 8; i++)
#pragma unroll
        for (int j = 0; j < 4; j++) acc[i][j] = 0.f;

    // ---- lin1 chunk 0: sage ----
    fillA(As, sage, blockRow, tid);
    fillB_t(Bs, lin1_W, tid);
    __syncthreads();
    mma_loop(acc, aAddr, bAddr);
    __syncthreads();

    // ---- lin1 chunk 1: att on the fly ----
    {
        const float4 ag4 = ((const float4*)attg)[lane];
        const float4 ab4 = ((const float4*)attb)[lane];
        const float4* Vg = (const float4*)(v + (size_t)blockRow * DDIM);
#pragma unroll
        for (int f = 0; f < 8; f++) {
            int i4 = tid + f * 256;
            int row = i4 >> 5;
            int g   = i4 & 31;
            size_t gr_ = (size_t)blockRow + row;
            float4 s = Vg[i4];
            const float w = w0[gr_] + it1[gr_] + it2[gr_];
            s.x *= w; s.y *= w; s.z *= w; s.w *= w;
            float sum = s.x + s.y + s.z + s.w;
            float sq  = s.x * s.x + s.y * s.y + s.z * s.z + s.w * s.w;
#pragma unroll
            for (int off = 16; off; off >>= 1) {
                sum += __shfl_xor_sync(0xFFFFFFFFu, sum, off);
                sq  += __shfl_xor_sync(0xFFFFFFFFu, sq,  off);
            }
            const float mean = sum * (1.f / 128.f);
            const float var  = sq * (1.f / 128.f) - mean * mean;
            const float rstd = rsqrtf(var + EPSF);
            float4 o;
            o.x = (s.x - mean) * rstd * ag4.x + ab4.x;
            o.y = (s.y - mean) * rstd * ag4.y + ab4.y;
            o.z = (s.z - mean) * rstd * ag4.z + ab4.z;
            o.w = (s.w - mean) * rstd * ag4.w + ab4.w;
            *(uint4*)(As + row * AST + g * 4) =
                make_uint4(f2tf(o.x), f2tf(o.y), f2tf(o.z), f2tf(o.w));
        }
    }
    fillB_t(Bs, lin1_W + DDIM * DDIM, tid);
    __syncthreads();
    mma_loop(acc, aAddr, bAddr);
    __syncthreads();

    // ---- h = LN(silu(acc + lin1_b)) -> tf32 into As ----
    stage_acc(CsB, acc, wr, wc, tg, gr);
    __syncthreads();
    ln_to_As(CsB, As, wid, lane, lin1_b, ln1g, ln1b);
    __syncthreads();

    // ---- lin2 ----
#pragma unroll
    for (int i = 0; i < 8; i++)
#pragma unroll
        for (int j = 0; j < 4; j++) acc[i][j] = 0.f;
    fillB_t(Bs, lin2_W, tid);
    __syncthreads();
    mma_loop(acc, aAddr, bAddr);
    __syncthreads();

    stage_acc(CsA, acc, wr, wc, tg, gr);
    __syncthreads();
    ln_epilogue(CsA, blockRow, wid, lane, lin2_b, x, ln2g, ln2b, out);
}

// ---------------- k/q retention weights (fp32, exact) ----------------
__global__ void kq_kernel(const float* __restrict__ x,
                          const float* __restrict__ Wk, const float* __restrict__ Wq,
                          float* __restrict__ w0)
{
    __shared__ float4 sk4[KDIM * 32];
    __shared__ float4 sq4[KDIM * 32];
    float* sk = (float*)sk4;
    float* sqm = (float*)sq4;
    for (int idx = threadIdx.x; idx < DDIM * KDIM; idx += blockDim.x) {
        int k = idx >> 4, j = idx & 15;
        sk[j * DDIM + k] = Wk[idx];
        sqm[j * DDIM + k] = Wq[idx];
    }
    __syncthreads();

    const int lane = threadIdx.x & 31;
    int warp = (blockIdx.x * blockDim.x + threadIdx.x) >> 5;
    const int nwarps = (gridDim.x * blockDim.x) >> 5;

    for (size_t r = warp; r < (size_t)MROWS; r += nwarps) {
        const float4 xv = ((const float4*)x)[r * 32 + lane];
        float pk[KDIM], pq[KDIM];
#pragma unroll
        for (int j = 0; j < KDIM; j++) {
            float4 wk = sk4[j * 32 + lane];
            float4 wq = sq4[j * 32 + lane];
            pk[j] = xv.x * wk.x + xv.y * wk.y + xv.z * wk.z + xv.w * wk.w;
            pq[j] = xv.x * wq.x + xv.y * wq.y + xv.z * wq.z + xv.w * wq.w;
        }
#pragma unroll
        for (int off = 16; off; off >>= 1) {
#pragma unroll
            for (int j = 0; j < KDIM; j++) {
                pk[j] += __shfl_xor_sync(0xFFFFFFFFu, pk[j], off);
                pq[j] += __shfl_xor_sync(0xFFFFFFFFu, pq[j], off);
            }
        }
        if (lane == 0) {
            float s = 0.f;
#pragma unroll
            for (int j = 0; j < KDIM; j++) s += pk[j] * pq[j];
            w0[r] = s * (1.f / (float)KDIM);
        }
    }
}

// ---------------- host ----------------
extern "C" void kernel_launch(void* const* d_in, const int* in_sizes, int n_in,
                              void* d_out, int out_size)
{
    const float* x          = (const float*)d_in[0];
    const int*   ei         = (const int*)  d_in[1];
    const float* ev         = (const float*)d_in[2];
    const float* sage_W     = (const float*)d_in[3];
    const float* sage_b     = (const float*)d_in[4];
    const float* sage_aggW  = (const float*)d_in[5];
    const float* sage_ln_g  = (const float*)d_in[6];
    const float* sage_ln_b  = (const float*)d_in[7];
    const float* att_Wk     = (const float*)d_in[8];
    const float* att_Wq     = (const float*)d_in[9];
    const float* att_Wv     = (const float*)d_in[10];
    const float* att_ln_g   = (const float*)d_in[11];
    const float* att_ln_b   = (const float*)d_in[12];
    const float* lin1_W     = (const float*)d_in[13];
    const float* lin1_b     = (const float*)d_in[14];
    const float* lin2_W     = (const float*)d_in[15];
    const float* lin2_b     = (const float*)d_in[16];
    const float* ln1_g      = (const float*)d_in[17];
    const float* ln1_b      = (const float*)d_in[18];
    const float* ln2_g      = (const float*)d_in[19];
    const float* ln2_b      = (const float*)d_in[20];
    float* out = (float*)d_out;

    float *v, *agg, *sage, *w0, *it1, *it2;
    cudaGetSymbolAddress((void**)&v,    g_v);
    cudaGetSymbolAddress((void**)&agg,  g_agg);
    cudaGetSymbolAddress((void**)&sage, g_sage);
    cudaGetSymbolAddress((void**)&w0,   g_w0);
    cudaGetSymbolAddress((void**)&it1,  g_it1);
    cudaGetSymbolAddress((void**)&it2,  g_it2);

    int *cnt2, *rowstart, *ecol;
    float *eval_;
    cudaGetSymbolAddress((void**)&cnt2,     g_cnt2);
    cudaGetSymbolAddress((void**)&rowstart, g_rowstart);
    cudaGetSymbolAddress((void**)&ecol,     g_ecol);
    cudaGetSymbolAddress((void**)&eval_,    g_eval);
    int* cnt = cnt2;
    int* cur = cnt2 + NNODES;

    cudaFuncSetAttribute(fused_front, cudaFuncAttributeMaxDynamicSharedMemorySize, GEMM_SMEM);
    cudaFuncSetAttribute(gemm_back,   cudaFuncAttributeMaxDynamicSharedMemorySize, GEMM_SMEM);

    const int gemmGrid = MROWS / 64; // 3125

    // launch 1: single memset clears cnt AND cur
    cudaMemsetAsync(cnt2, 0, 2 * NNODES * sizeof(int), 0);
    // launch 2-4: CSR build
    hist_kernel<<<(EEDGES + 255) / 256, 256>>>(ei, cnt);
    scan_kernel<<<1, 1024>>>(cnt, rowstart);
    scatter_kernel<<<(EEDGES + 255) / 256, 256>>>(ei, ev, rowstart, cur, ecol, eval_);

    // launch 5: merged spmm, blockIdx.y = l (slice-major order preserved)
    {
        dim3 grid((NNODES * 32 + 255) / 256, LDIM);
        spmm_all<<<grid, 256>>>(rowstart, ecol, eval_, x, agg);
    }

    // launch 6 (PROFILED): fused front GEMM
    fused_front<<<gemmGrid, 256, GEMM_SMEM>>>(x, agg, sage_W, att_Wv, sage_aggW,
                                              sage_b, sage_ln_g, sage_ln_b, v, sage);

    // retention base weights (fp32 exact)
    kq_kernel<<<1480, 256>>>(x, att_Wk, att_Wq, w0);

    // retention iterations
    ret_gather<<<(NNODES * 32 + 255) / 256, 256>>>(rowstart, ecol, eval_, w0, it1);
    ret_gather<<<(NNODES * 32 + 255) / 256, 256>>>(rowstart, ecol, eval_, it1, it2);

    // lin1 (+att) chained into lin2
    gemm_back<<<gemmGrid, 256, GEMM_SMEM>>>(sage, v, w0, it1, it2,
                                            att_ln_g, att_ln_b,
                                            lin1_W, lin1_b, ln1_g, ln1_b,
                                            lin2_W, lin2_b,
                                            x, ln2_g, ln2_b, out);
}

// round 16
// speedup vs baseline: 1.0148x; 1.0148x over previous
#include <cuda_runtime.h>
#include <math.h>

#define NNODES 50000
#define LDIM   4
#define DDIM   128
#define KDIM   16
#define EEDGES 800000
#define MROWS  (LDIM * NNODES)        // 200000, multiple of 64
#define DECAYF 0.7f
#define EPSF   1e-5f

// ---------------- scratch (device globals; no allocation) ----------------
__device__ float g_v   [MROWS * DDIM];
__device__ float g_agg [MROWS * DDIM];
__device__ float g_sage[MROWS * DDIM];
__device__ float g_w0 [MROWS];
__device__ float g_it1[MROWS];
__device__ float g_it2[MROWS];
__device__ unsigned g_bt[6 * DDIM * DDIM];   // transposed weights [n][k], tf32 bits

// CSR build scratch (cnt and cur share one buffer -> one memset)
__device__ int   g_cnt2[2 * NNODES];
__device__ int   g_rowstart[NNODES + 1];
__device__ int   g_ecol[EEDGES];
__device__ float g_eval[EEDGES];

__device__ __forceinline__ unsigned f2tf(float f)
{
    unsigned u;
    asm("cvt.rna.tf32.f32 %0, %1;" : "=r"(u) : "f"(f));
    return u;
}

// ================= weight transpose + tf32 convert (once, tiny) ==============
struct SixPtr { const float* p[6]; };

__global__ void transpose_kernel(SixPtr srcs, unsigned* __restrict__ dst)
{
    __shared__ float tile[32][33];
    const int m = blockIdx.z;
    const float* src = srcs.p[m];
    unsigned* d = dst + m * DDIM * DDIM;
    const int bx = blockIdx.x * 32;
    const int by = blockIdx.y * 32;
    const int tx = threadIdx.x, ty = threadIdx.y;
#pragma unroll
    for (int j = 0; j < 32; j += 8)
        tile[ty + j][tx] = src[(by + ty + j) * DDIM + bx + tx];
    __syncthreads();
#pragma unroll
    for (int j = 0; j < 32; j += 8)
        d[(bx + ty + j) * DDIM + by + tx] = f2tf(tile[tx][ty + j]);
}

// ================= CSR construction =================
__global__ void hist_kernel(const int* __restrict__ ei, int* __restrict__ cnt)
{
    int e = blockIdx.x * blockDim.x + threadIdx.x;
    if (e < EEDGES) atomicAdd(&cnt[ei[e]], 1);
}

__global__ void scan_kernel(const int* __restrict__ cnt, int* __restrict__ rowstart)
{
    const int T = 1024;
    __shared__ int partial[T];
    const int tid = threadIdx.x;
    const int chunk = (NNODES + T - 1) / T;
    const int base = tid * chunk;
    int s = 0;
    for (int i = 0; i < chunk; i++) {
        int idx = base + i;
        if (idx < NNODES) s += cnt[idx];
    }
    partial[tid] = s;
    __syncthreads();
    for (int off = 1; off < T; off <<= 1) {
        int v = (tid >= off) ? partial[tid - off] : 0;
        __syncthreads();
        partial[tid] += v;
        __syncthreads();
    }
    int run = (tid == 0) ? 0 : partial[tid - 1];
    for (int i = 0; i < chunk; i++) {
        int idx = base + i;
        if (idx < NNODES) { rowstart[idx] = run; run += cnt[idx]; }
    }
    if (tid == T - 1) rowstart[NNODES] = run;
}

__global__ void scatter_kernel(const int* __restrict__ ei, const float* __restrict__ ev,
                               const int* __restrict__ rowstart, int* __restrict__ cur,
                               int* __restrict__ ecol, float* __restrict__ eval_)
{
    int e = blockIdx.x * blockDim.x + threadIdx.x;
    if (e >= EEDGES) return;
    const int r = ei[e];
    const int pos = rowstart[r] + atomicAdd(&cur[r], 1);
    ecol[pos]  = ei[EEDGES + e];
    eval_[pos] = ev[e];
}

// ================= gather spmm: merged, blockIdx.y = l (slice-major order) ===
__global__ void __launch_bounds__(256) spmm_all(
    const int* __restrict__ rowstart,
    const int* __restrict__ ecol, const float* __restrict__ eval_,
    const float* __restrict__ x, float* __restrict__ agg)
{
    const int l = blockIdx.y;
    const int row = (blockIdx.x * blockDim.x + threadIdx.x) >> 5;
    const int lane = threadIdx.x & 31;
    if (row >= NNODES) return;

    const int s = rowstart[row];
    const int e = rowstart[row + 1];
    const float4* xl = (const float4*)x + (size_t)l * NNODES * 32;

    float4 acc = make_float4(0.f, 0.f, 0.f, 0.f);
    int i = s;
    for (; i + 4 <= e; i += 4) {
        const int   c0 = ecol[i],   c1 = ecol[i+1], c2 = ecol[i+2], c3 = ecol[i+3];
        const float v0 = eval_[i],  v1 = eval_[i+1], v2 = eval_[i+2], v3 = eval_[i+3];
        float4 x0 = xl[(size_t)c0 * 32 + lane];
        float4 x1 = xl[(size_t)c1 * 32 + lane];
        float4 x2 = xl[(size_t)c2 * 32 + lane];
        float4 x3 = xl[(size_t)c3 * 32 + lane];
        acc.x += v0 * x0.x; acc.y += v0 * x0.y; acc.z += v0 * x0.z; acc.w += v0 * x0.w;
        acc.x += v1 * x1.x; acc.y += v1 * x1.y; acc.z += v1 * x1.z; acc.w += v1 * x1.w;
        acc.x += v2 * x2.x; acc.y += v2 * x2.y; acc.z += v2 * x2.z; acc.w += v2 * x2.w;
        acc.x += v3 * x3.x; acc.y += v3 * x3.y; acc.z += v3 * x3.z; acc.w += v3 * x3.w;
    }
    for (; i < e; i++) {
        const int c0 = ecol[i];
        const float v0 = eval_[i];
        float4 x0 = xl[(size_t)c0 * 32 + lane];
        acc.x += v0 * x0.x; acc.y += v0 * x0.y; acc.z += v0 * x0.z; acc.w += v0 * x0.w;
    }
    ((float4*)agg)[((size_t)l * NNODES + row) * 32 + lane] = acc;
}

// ================= retention spmm on [L,N] weights (gather) =================
__global__ void __launch_bounds__(256) ret_gather(
    const int* __restrict__ rowstart,
    const int* __restrict__ ecol, const float* __restrict__ eval_,
    const float* __restrict__ src, float* __restrict__ dst)
{
    const int row = (blockIdx.x * blockDim.x + threadIdx.x) >> 5;
    const int lane = threadIdx.x & 31;
    if (row >= NNODES) return;
    const int s = rowstart[row];
    const int e = rowstart[row + 1];

    float a0 = 0.f, a1 = 0.f, a2 = 0.f, a3 = 0.f;
    for (int i = s + lane; i < e; i += 32) {
        const int c = ecol[i];
        const float v = DECAYF * eval_[i];
        a0 += v * src[c];
        a1 += v * src[NNODES + c];
        a2 += v * src[2 * NNODES + c];
        a3 += v * src[3 * NNODES + c];
    }
#pragma unroll
    for (int off = 16; off; off >>= 1) {
        a0 += __shfl_xor_sync(0xFFFFFFFFu, a0, off);
        a1 += __shfl_xor_sync(0xFFFFFFFFu, a1, off);
        a2 += __shfl_xor_sync(0xFFFFFFFFu, a2, off);
        a3 += __shfl_xor_sync(0xFFFFFFFFu, a3, off);
    }
    if (lane == 0) {
        dst[row]              = a0;
        dst[NNODES + row]     = a1;
        dst[2 * NNODES + row] = a2;
        dst[3 * NNODES + row] = a3;
    }
}

// ================= common MMA helpers =================
#define AST 132
#define BST 132
#define GEMM_SMEM ((64 * AST + 128 * BST) * 4)   // 101376 bytes

__device__ __forceinline__ void mma8(float* c, const unsigned* a, unsigned b0, unsigned b1)
{
    asm volatile(
        "mma.sync.aligned.m16n8k8.row.col.f32.tf32.tf32.f32 "
        "{%0,%1,%2,%3},{%4,%5,%6,%7},{%8,%9},{%0,%1,%2,%3};"
        : "+f"(c[0]), "+f"(c[1]), "+f"(c[2]), "+f"(c[3])
        : "r"(a[0]), "r"(a[1]), "r"(a[2]), "r"(a[3]), "r"(b0), "r"(b1));
}

#define LDSM4(r, addr) \
    asm volatile("ldmatrix.sync.aligned.m8n8.x4.shared.b16 {%0,%1,%2,%3}, [%4];" \
        : "=r"((r)[0]), "=r"((r)[1]), "=r"((r)[2]), "=r"((r)[3]) : "r"(addr))

__device__ __forceinline__ void fillA(unsigned* As, const float* A, int blockRow, int tid)
{
    const float4* Ag = (const float4*)(A + (size_t)blockRow * DDIM);
#pragma unroll
    for (int f = 0; f < 8; f++) {
        int i4 = tid + f * 256;
        float4 t = Ag[i4];
        int e = i4 * 4;
        *(uint4*)(As + (e >> 7) * AST + (e & 127)) =
            make_uint4(f2tf(t.x), f2tf(t.y), f2tf(t.z), f2tf(t.w));
    }
}

// B-tile fill: weights pre-converted to tf32 bits — raw uint4 copy
__device__ __forceinline__ void fillB(unsigned* Bs, const unsigned* Bt, int tid)
{
    const uint4* Bg = (const uint4*)Bt;
#pragma unroll
    for (int f = 0; f < 16; f++) {
        int i4 = tid + f * 256;
        uint4 t = Bg[i4];
        int e = i4 * 4;
        *(uint4*)(Bs + (e >> 7) * BST + (e & 127)) = t;
    }
}

__device__ __forceinline__ void mma_loop(float acc[8][4], unsigned aAddr, unsigned bAddr)
{
#pragma unroll
    for (int k8 = 0; k8 < 16; k8++) {
        const unsigned ko = k8 * 32;
        unsigned af[4], bf[4][4];
        LDSM4(af, aAddr + ko);
        LDSM4(bf[0], bAddr + ko);
        LDSM4(bf[1], bAddr + 16 * BST * 4 + ko);
        LDSM4(bf[2], bAddr + 32 * BST * 4 + ko);
        LDSM4(bf[3], bAddr + 48 * BST * 4 + ko);
#pragma unroll
        for (int nt = 0; nt < 8; nt++)
            mma8(acc[nt], af, bf[nt >> 1][(nt & 1) * 2], bf[nt >> 1][(nt & 1) * 2 + 1]);
    }
}

// LN(silu(.)) -> global store
__device__ __forceinline__ void ln_epilogue(
    const float* Cs, int blockRow, int wid, int lane,
    const float* bias, const float* addb,
    const float* lng, const float* lnb, float* C)
{
    float4 bias4 = make_float4(0.f, 0.f, 0.f, 0.f);
    if (bias) bias4 = ((const float4*)bias)[lane];
    const float4 g4 = ((const float4*)lng)[lane];
    const float4 b4 = ((const float4*)lnb)[lane];
#pragma unroll
    for (int i = 0; i < 8; i++) {
        const int r = wid * 8 + i;
        const size_t gr_ = (size_t)blockRow + r;
        float4 t = *(const float4*)(Cs + r * AST + lane * 4);
        t.x += bias4.x; t.y += bias4.y; t.z += bias4.z; t.w += bias4.w;
        if (addb) {
            float4 ad = ((const float4*)addb)[gr_ * 32 + lane];
            t.x += ad.x; t.y += ad.y; t.z += ad.z; t.w += ad.w;
        }
        float4 s;
        s.x = t.x / (1.f + expf(-t.x));
        s.y = t.y / (1.f + expf(-t.y));
        s.z = t.z / (1.f + expf(-t.z));
        s.w = t.w / (1.f + expf(-t.w));
        float sum = s.x + s.y + s.z + s.w;
        float sq  = s.x * s.x + s.y * s.y + s.z * s.z + s.w * s.w;
#pragma unroll
        for (int off = 16; off; off >>= 1) {
            sum += __shfl_xor_sync(0xFFFFFFFFu, sum, off);
            sq  += __shfl_xor_sync(0xFFFFFFFFu, sq,  off);
        }
        const float mean = sum * (1.f / 128.f);
        const float var  = sq * (1.f / 128.f) - mean * mean;
        const float rstd = rsqrtf(var + EPSF);
        float4 o;
        o.x = (s.x - mean) * rstd * g4.x + b4.x;
        o.y = (s.y - mean) * rstd * g4.y + b4.y;
        o.z = (s.z - mean) * rstd * g4.z + b4.z;
        o.w = (s.w - mean) * rstd * g4.w + b4.w;
        ((float4*)C)[gr_ * 32 + lane] = o;
    }
}

// LN(silu(.)) -> tf32 into As tile (for chained GEMM)
__device__ __forceinline__ void ln_to_As(
    const float* CsB, unsigned* As, int wid, int lane,
    const float* bias, const float* lng, const float* lnb)
{
    float4 bias4 = make_float4(0.f, 0.f, 0.f, 0.f);
    if (bias) bias4 = ((const float4*)bias)[lane];
    const float4 g4 = ((const float4*)lng)[lane];
    const float4 b4 = ((const float4*)lnb)[lane];
#pragma unroll
    for (int i = 0; i < 8; i++) {
        const int r = wid * 8 + i;
        float4 t = *(const float4*)(CsB + r * AST + lane * 4);
        t.x += bias4.x; t.y += bias4.y; t.z += bias4.z; t.w += bias4.w;
        float4 s;
        s.x = t.x / (1.f + expf(-t.x));
        s.y = t.y / (1.f + expf(-t.y));
        s.z = t.z / (1.f + expf(-t.z));
        s.w = t.w / (1.f + expf(-t.w));
        float sum = s.x + s.y + s.z + s.w;
        float sq  = s.x * s.x + s.y * s.y + s.z * s.z + s.w * s.w;
#pragma unroll
        for (int off = 16; off; off >>= 1) {
            sum += __shfl_xor_sync(0xFFFFFFFFu, sum, off);
            sq  += __shfl_xor_sync(0xFFFFFFFFu, sq,  off);
        }
        const float mean = sum * (1.f / 128.f);
        const float var  = sq * (1.f / 128.f) - mean * mean;
        const float rstd = rsqrtf(var + EPSF);
        float4 o;
        o.x = (s.x - mean) * rstd * g4.x + b4.x;
        o.y = (s.y - mean) * rstd * g4.y + b4.y;
        o.z = (s.z - mean) * rstd * g4.z + b4.z;
        o.w = (s.w - mean) * rstd * g4.w + b4.w;
        *(uint4*)(As + r * AST + lane * 4) =
            make_uint4(f2tf(o.x), f2tf(o.y), f2tf(o.z), f2tf(o.w));
    }
}

__device__ __forceinline__ void stage_acc(float* Cs, const float acc[8][4],
                                          int wr, int wc, int tg, int gr)
{
    const int r0 = wr * 16 + gr;
#pragma unroll
    for (int nt = 0; nt < 8; nt++) {
        const int c = wc * 64 + nt * 8 + 2 * tg;
        *(float2*)(Cs + r0 * AST + c)       = make_float2(acc[nt][0], acc[nt][1]);
        *(float2*)(Cs + (r0 + 8) * AST + c) = make_float2(acc[nt][2], acc[nt][3]);
    }
}

// ================= fused_front: v = x@Wv ; sage = LN(silu(x@W + b + agg@aggW)) =
__global__ void __launch_bounds__(256, 2) fused_front(
    const float* __restrict__ x, const float* __restrict__ agg,
    const unsigned* __restrict__ bt, const float* __restrict__ sage_b,
    const float* __restrict__ lng, const float* __restrict__ lnb,
    float* __restrict__ v, float* __restrict__ sage)
{
    extern __shared__ unsigned smem_u[];
    unsigned* As = smem_u;
    unsigned* Bs = smem_u + 64 * AST;
    float* Cs = (float*)smem_u;

    const int tid  = threadIdx.x;
    const int lane = tid & 31;
    const int wid  = tid >> 5;
    const int wr   = wid & 3;
    const int wc   = wid >> 2;
    const int tg   = lane & 3;
    const int gr   = lane >> 2;
    const int blockRow = blockIdx.x * 64;

    const unsigned sbase = (unsigned)__cvta_generic_to_shared(smem_u);
    const unsigned aAddr = sbase +
        ((wr * 16 + (lane & 15)) * AST + (lane >> 4) * 4) * 4u;
    const unsigned bAddr = sbase + 64u * AST * 4u +
        ((wc * 64 + (lane >> 4) * 8 + (lane & 7)) * BST + ((lane >> 3) & 1) * 4) * 4u;

    float acc[8][4];

    // pass 1: v = x @ Wv
    fillA(As, x, blockRow, tid);
    fillB(Bs, bt + 1 * DDIM * DDIM, tid);
    __syncthreads();
#pragma unroll
    for (int i = 0; i < 8; i++)
#pragma unroll
        for (int j = 0; j < 4; j++) acc[i][j] = 0.f;
    mma_loop(acc, aAddr, bAddr);
    {
        const int r0 = blockRow + wr * 16 + gr;
#pragma unroll
        for (int nt = 0; nt < 8; nt++) {
            const int c = wc * 64 + nt * 8 + 2 * tg;
            ((float2*)v)[(size_t)r0 * 64 + (c >> 1)]       = make_float2(acc[nt][0], acc[nt][1]);
            ((float2*)v)[(size_t)(r0 + 8) * 64 + (c >> 1)] = make_float2(acc[nt][2], acc[nt][3]);
        }
    }
    __syncthreads();

    // pass 2: acc = x @ sage_W   (As still holds x)
    fillB(Bs, bt + 0 * DDIM * DDIM, tid);
    __syncthreads();
#pragma unroll
    for (int i = 0; i < 8; i++)
#pragma unroll
        for (int j = 0; j < 4; j++) acc[i][j] = 0.f;
    mma_loop(acc, aAddr, bAddr);
    __syncthreads();

    // pass 3: acc += agg @ aggW
    fillA(As, agg, blockRow, tid);
    fillB(Bs, bt + 2 * DDIM * DDIM, tid);
    __syncthreads();
    mma_loop(acc, aAddr, bAddr);
    __syncthreads();

    stage_acc(Cs, acc, wr, wc, tg, gr);
    __syncthreads();
    ln_epilogue(Cs, blockRow, wid, lane, sage_b, nullptr, lng, lnb, sage);
}

// ================= gemm_back: lin1 (+att on the fly) chained into lin2 =======
__global__ void __launch_bounds__(256, 2) gemm_back(
    const float* __restrict__ sage, const float* __restrict__ v,
    const float* __restrict__ w0, const float* __restrict__ it1,
    const float* __restrict__ it2,
    const float* __restrict__ attg, const float* __restrict__ attb,
    const unsigned* __restrict__ bt_lin1, const float* __restrict__ lin1_b,
    const float* __restrict__ ln1g, const float* __restrict__ ln1b,
    const unsigned* __restrict__ bt_lin2, const float* __restrict__ lin2_b,
    const float* __restrict__ x,
    const float* __restrict__ ln2g, const float* __restrict__ ln2b,
    float* __restrict__ out)
{
    extern __shared__ unsigned smem_u[];
    unsigned* As = smem_u;
    unsigned* Bs = smem_u + 64 * AST;
    float* CsA = (float*)smem_u;
    float* CsB = (float*)(smem_u + 64 * AST);

    const int tid  = threadIdx.x;
    const int lane = tid & 31;
    const int wid  = tid >> 5;
    const int wr   = wid & 3;
    const int wc   = wid >> 2;
    const int tg   = lane & 3;
    const int gr   = lane >> 2;
    const int blockRow = blockIdx.x * 64;

    const unsigned sbase = (unsigned)__cvta_generic_to_shared(smem_u);
    const unsigned aAddr = sbase +
        ((wr * 16 + (lane & 15)) * AST + (lane >> 4) * 4) * 4u;
    const unsigned bAddr = sbase + 64u * AST * 4u +
        ((wc * 64 + (lane >> 4) * 8 + (lane & 7)) * BST + ((lane >> 3) & 1) * 4) * 4u;

    float acc[8][4];
#pragma unroll
    for (int i = 0; i < 8; i++)
#pragma unroll
        for (int j = 0; j < 4; j++) acc[i][j] = 0.f;

    // ---- lin1 chunk 0: sage ----
    fillA(As, sage, blockRow, tid);
    fillB(Bs, bt_lin1, tid);
    __syncthreads();
    mma_loop(acc, aAddr, bAddr);
    __syncthreads();

    // ---- lin1 chunk 1: att on the fly ----
    {
        const float4 ag4 = ((const float4*)attg)[lane];
        const float4 ab4 = ((const float4*)attb)[lane];
        const float4* Vg = (const float4*)(v + (size_t)blockRow * DDIM);
#pragma unroll
        for (int f = 0; f < 8; f++) {
            int i4 = tid + f * 256;
            int row = i4 >> 5;
            int g   = i4 & 31;
            size_t gr_ = (size_t)blockRow + row;
            float4 s = Vg[i4];
            const float w = w0[gr_] + it1[gr_] + it2[gr_];
            s.x *= w; s.y *= w; s.z *= w; s.w *= w;
            float sum = s.x + s.y + s.z + s.w;
            float sq  = s.x * s.x + s.y * s.y + s.z * s.z + s.w * s.w;
#pragma unroll
            for (int off = 16; off; off >>= 1) {
                sum += __shfl_xor_sync(0xFFFFFFFFu, sum, off);
                sq  += __shfl_xor_sync(0xFFFFFFFFu, sq,  off);
            }
            const float mean = sum * (1.f / 128.f);
            const float var  = sq * (1.f / 128.f) - mean * mean;
            const float rstd = rsqrtf(var + EPSF);
            float4 o;
            o.x = (s.x - mean) * rstd * ag4.x + ab4.x;
            o.y = (s.y - mean) * rstd * ag4.y + ab4.y;
            o.z = (s.z - mean) * rstd * ag4.z + ab4.z;
            o.w = (s.w - mean) * rstd * ag4.w + ab4.w;
            *(uint4*)(As + row * AST + g * 4) =
                make_uint4(f2tf(o.x), f2tf(o.y), f2tf(o.z), f2tf(o.w));
        }
    }
    fillB(Bs, bt_lin1 + DDIM * DDIM, tid);
    __syncthreads();
    mma_loop(acc, aAddr, bAddr);
    __syncthreads();

    // ---- h = LN(silu(acc + lin1_b)) -> tf32 into As ----
    stage_acc(CsB, acc, wr, wc, tg, gr);
    __syncthreads();
    ln_to_As(CsB, As, wid, lane, lin1_b, ln1g, ln1b);
    __syncthreads();

    // ---- lin2 ----
#pragma unroll
    for (int i = 0; i < 8; i++)
#pragma unroll
        for (int j = 0; j < 4; j++) acc[i][j] = 0.f;
    fillB(Bs, bt_lin2, tid);
    __syncthreads();
    mma_loop(acc, aAddr, bAddr);
    __syncthreads();

    stage_acc(CsA, acc, wr, wc, tg, gr);
    __syncthreads();
    ln_epilogue(CsA, blockRow, wid, lane, lin2_b, x, ln2g, ln2b, out);
}

// ---------------- k/q retention weights (fp32, exact) ----------------
__global__ void kq_kernel(const float* __restrict__ x,
                          const float* __restrict__ Wk, const float* __restrict__ Wq,
                          float* __restrict__ w0)
{
    __shared__ float4 sk4[KDIM * 32];
    __shared__ float4 sq4[KDIM * 32];
    float* sk = (float*)sk4;
    float* sqm = (float*)sq4;
    for (int idx = threadIdx.x; idx < DDIM * KDIM; idx += blockDim.x) {
        int k = idx >> 4, j = idx & 15;
        sk[j * DDIM + k] = Wk[idx];
        sqm[j * DDIM + k] = Wq[idx];
    }
    __syncthreads();

    const int lane = threadIdx.x & 31;
    int warp = (blockIdx.x * blockDim.x + threadIdx.x) >> 5;
    const int nwarps = (gridDim.x * blockDim.x) >> 5;

    for (size_t r = warp; r < (size_t)MROWS; r += nwarps) {
        const float4 xv = ((const float4*)x)[r * 32 + lane];
        float pk[KDIM], pq[KDIM];
#pragma unroll
        for (int j = 0; j < KDIM; j++) {
            float4 wk = sk4[j * 32 + lane];
            float4 wq = sq4[j * 32 + lane];
            pk[j] = xv.x * wk.x + xv.y * wk.y + xv.z * wk.z + xv.w * wk.w;
            pq[j] = xv.x * wq.x + xv.y * wq.y + xv.z * wq.z + xv.w * wq.w;
        }
#pragma unroll
        for (int off = 16; off; off >>= 1) {
#pragma unroll
            for (int j = 0; j < KDIM; j++) {
                pk[j] += __shfl_xor_sync(0xFFFFFFFFu, pk[j], off);
                pq[j] += __shfl_xor_sync(0xFFFFFFFFu, pq[j], off);
            }
        }
        if (lane == 0) {
            float s = 0.f;
#pragma unroll
            for (int j = 0; j < KDIM; j++) s += pk[j] * pq[j];
            w0[r] = s * (1.f / (float)KDIM);
        }
    }
}

// ---------------- host ----------------
extern "C" void kernel_launch(void* const* d_in, const int* in_sizes, int n_in,
                              void* d_out, int out_size)
{
    const float* x          = (const float*)d_in[0];
    const int*   ei         = (const int*)  d_in[1];
    const float* ev         = (const float*)d_in[2];
    const float* sage_W     = (const float*)d_in[3];
    const float* sage_b     = (const float*)d_in[4];
    const float* sage_aggW  = (const float*)d_in[5];
    const float* sage_ln_g  = (const float*)d_in[6];
    const float* sage_ln_b  = (const float*)d_in[7];
    const float* att_Wk     = (const float*)d_in[8];
    const float* att_Wq     = (const float*)d_in[9];
    const float* att_Wv     = (const float*)d_in[10];
    const float* att_ln_g   = (const float*)d_in[11];
    const float* att_ln_b   = (const float*)d_in[12];
    const float* lin1_W     = (const float*)d_in[13];
    const float* lin1_b     = (const float*)d_in[14];
    const float* lin2_W     = (const float*)d_in[15];
    const float* lin2_b     = (const float*)d_in[16];
    const float* ln1_g      = (const float*)d_in[17];
    const float* ln1_b      = (const float*)d_in[18];
    const float* ln2_g      = (const float*)d_in[19];
    const float* ln2_b      = (const float*)d_in[20];
    float* out = (float*)d_out;

    float *v, *agg, *sage, *w0, *it1, *it2;
    unsigned *bt;
    cudaGetSymbolAddress((void**)&v,    g_v);
    cudaGetSymbolAddress((void**)&agg,  g_agg);
    cudaGetSymbolAddress((void**)&sage, g_sage);
    cudaGetSymbolAddress((void**)&w0,   g_w0);
    cudaGetSymbolAddress((void**)&it1,  g_it1);
    cudaGetSymbolAddress((void**)&it2,  g_it2);
    cudaGetSymbolAddress((void**)&bt,   g_bt);

    int *cnt2, *rowstart, *ecol;
    float *eval_;
    cudaGetSymbolAddress((void**)&cnt2,     g_cnt2);
    cudaGetSymbolAddress((void**)&rowstart, g_rowstart);
    cudaGetSymbolAddress((void**)&ecol,     g_ecol);
    cudaGetSymbolAddress((void**)&eval_,    g_eval);
    int* cnt = cnt2;
    int* cur = cnt2 + NNODES;

    cudaFuncSetAttribute(fused_front, cudaFuncAttributeMaxDynamicSharedMemorySize, GEMM_SMEM);
    cudaFuncSetAttribute(gemm_back,   cudaFuncAttributeMaxDynamicSharedMemorySize, GEMM_SMEM);

    const int gemmGrid = MROWS / 64; // 3125

    // launch 1: weight transpose + tf32 convert (tiny, one-time)
    SixPtr sp;
    sp.p[0] = sage_W; sp.p[1] = att_Wv; sp.p[2] = sage_aggW;
    sp.p[3] = lin1_W; sp.p[4] = lin1_W + DDIM * DDIM; sp.p[5] = lin2_W;
    {
        dim3 tg(4, 4, 6), tb(32, 8);
        transpose_kernel<<<tg, tb>>>(sp, bt);
    }

    // launch 2: single memset clears cnt AND cur
    cudaMemsetAsync(cnt2, 0, 2 * NNODES * sizeof(int), 0);
    // launch 3-5: CSR build
    hist_kernel<<<(EEDGES + 255) / 256, 256>>>(ei, cnt);
    scan_kernel<<<1, 1024>>>(cnt, rowstart);
    scatter_kernel<<<(EEDGES + 255) / 256, 256>>>(ei, ev, rowstart, cur, ecol, eval_);

    // launch 6 (PROFILED): merged spmm, blockIdx.y = l (slice-major order)
    {
        dim3 grid((NNODES * 32 + 255) / 256, LDIM);
        spmm_all<<<grid, 256>>>(rowstart, ecol, eval_, x, agg);
    }

    // fused front GEMM: v = x@Wv ; sage = LN(silu(x@sage_W + b + agg@aggW))
    fused_front<<<gemmGrid, 256, GEMM_SMEM>>>(x, agg, bt, sage_b,
                                              sage_ln_g, sage_ln_b, v, sage);

    // retention base weights (fp32 exact)
    kq_kernel<<<1480, 256>>>(x, att_Wk, att_Wq, w0);

    // retention iterations
    ret_gather<<<(NNODES * 32 + 255) / 256, 256>>>(rowstart, ecol, eval_, w0, it1);
    ret_gather<<<(NNODES * 32 + 255) / 256, 256>>>(rowstart, ecol, eval_, it1, it2);

    // lin1 (+att) chained into lin2
    gemm_back<<<gemmGrid, 256, GEMM_SMEM>>>(sage, v, w0, it1, it2,
                                            att_ln_g, att_ln_b,
                                            lin1_W ? (bt + 3 * DDIM * DDIM) : nullptr, lin1_b,
                                            ln1_g, ln1_b,
                                            bt + 5 * DDIM * DDIM, lin2_b,
                                            x, ln2_g, ln2_b, out);
}

// round 17
// speedup vs baseline: 1.0869x; 1.0710x over previous
#include <cuda_runtime.h>
#include <math.h>

#define NNODES 50000
#define LDIM   4
#define DDIM   128
#define KDIM   16
#define EEDGES 800000
#define MROWS  (LDIM * NNODES)        // 200000, multiple of 64
#define DECAYF 0.7f
#define EPSF   1e-5f

// ---------------- scratch (device globals; no allocation) ----------------
__device__ float g_v   [MROWS * DDIM];
__device__ float g_agg [MROWS * DDIM];
__device__ float g_w0 [MROWS];
__device__ float g_it1[MROWS];
__device__ float g_it2[MROWS];
__device__ unsigned g_bt[6 * DDIM * DDIM];   // transposed weights [n][k], tf32 bits

// CSR build scratch (cnt and cur share one buffer -> one memset)
__device__ int   g_cnt2[2 * NNODES];
__device__ int   g_rowstart[NNODES + 1];
__device__ int   g_ecol[EEDGES];
__device__ float g_eval[EEDGES];

__device__ __forceinline__ unsigned f2tf(float f)
{
    unsigned u;
    asm("cvt.rna.tf32.f32 %0, %1;" : "=r"(u) : "f"(f));
    return u;
}

// ================= prep: weight transpose+tf32 AND clear cnt buffers =========
struct SixPtr { const float* p[6]; };
#define PREP_TRANS_BLOCKS 96                      // 6 mats x 16 tiles
#define PREP_CLEAR_BLOCKS ((2 * NNODES + 255) / 256)

__global__ void prep_kernel(SixPtr srcs, unsigned* __restrict__ dst,
                            int* __restrict__ cnt2)
{
    const int b = blockIdx.x;
    if (b < PREP_TRANS_BLOCKS) {
        __shared__ float tile[32][33];
        const int m = b >> 4;
        const int r = b & 15;
        const int bx = (r & 3) * 32;
        const int by = (r >> 2) * 32;
        const int tx = threadIdx.x & 31;
        const int ty = threadIdx.x >> 5;   // 0..7
        const float* src = srcs.p[m];
        unsigned* d = dst + m * DDIM * DDIM;
#pragma unroll
        for (int j = 0; j < 32; j += 8)
            tile[ty + j][tx] = src[(by + ty + j) * DDIM + bx + tx];
        __syncthreads();
#pragma unroll
        for (int j = 0; j < 32; j += 8)
            d[(bx + ty + j) * DDIM + by + tx] = f2tf(tile[tx][ty + j]);
    } else {
        int i = (b - PREP_TRANS_BLOCKS) * 256 + threadIdx.x;
        if (i < 2 * NNODES) cnt2[i] = 0;
    }
}

// ================= CSR construction =================
__global__ void hist_kernel(const int* __restrict__ ei, int* __restrict__ cnt)
{
    int e = blockIdx.x * blockDim.x + threadIdx.x;
    if (e < EEDGES) atomicAdd(&cnt[ei[e]], 1);
}

__global__ void scan_kernel(const int* __restrict__ cnt, int* __restrict__ rowstart)
{
    const int T = 1024;
    __shared__ int partial[T];
    const int tid = threadIdx.x;
    const int chunk = (NNODES + T - 1) / T;
    const int base = tid * chunk;
    int s = 0;
    for (int i = 0; i < chunk; i++) {
        int idx = base + i;
        if (idx < NNODES) s += cnt[idx];
    }
    partial[tid] = s;
    __syncthreads();
    for (int off = 1; off < T; off <<= 1) {
        int v = (tid >= off) ? partial[tid - off] : 0;
        __syncthreads();
        partial[tid] += v;
        __syncthreads();
    }
    int run = (tid == 0) ? 0 : partial[tid - 1];
    for (int i = 0; i < chunk; i++) {
        int idx = base + i;
        if (idx < NNODES) { rowstart[idx] = run; run += cnt[idx]; }
    }
    if (tid == T - 1) rowstart[NNODES] = run;
}

__global__ void scatter_kernel(const int* __restrict__ ei, const float* __restrict__ ev,
                               const int* __restrict__ rowstart, int* __restrict__ cur,
                               int* __restrict__ ecol, float* __restrict__ eval_)
{
    int e = blockIdx.x * blockDim.x + threadIdx.x;
    if (e >= EEDGES) return;
    const int r = ei[e];
    const int pos = rowstart[r] + atomicAdd(&cur[r], 1);
    ecol[pos]  = ei[EEDGES + e];
    eval_[pos] = ev[e];
}

// ================= gather spmm: merged, blockIdx.y = l (slice-major order) ===
__global__ void __launch_bounds__(256) spmm_all(
    const int* __restrict__ rowstart,
    const int* __restrict__ ecol, const float* __restrict__ eval_,
    const float* __restrict__ x, float* __restrict__ agg)
{
    const int l = blockIdx.y;
    const int row = (blockIdx.x * blockDim.x + threadIdx.x) >> 5;
    const int lane = threadIdx.x & 31;
    if (row >= NNODES) return;

    const int s = rowstart[row];
    const int e = rowstart[row + 1];
    const float4* xl = (const float4*)x + (size_t)l * NNODES * 32;

    float4 acc = make_float4(0.f, 0.f, 0.f, 0.f);
    int i = s;
    for (; i + 4 <= e; i += 4) {
        const int   c0 = ecol[i],   c1 = ecol[i+1], c2 = ecol[i+2], c3 = ecol[i+3];
        const float v0 = eval_[i],  v1 = eval_[i+1], v2 = eval_[i+2], v3 = eval_[i+3];
        float4 x0 = xl[(size_t)c0 * 32 + lane];
        float4 x1 = xl[(size_t)c1 * 32 + lane];
        float4 x2 = xl[(size_t)c2 * 32 + lane];
        float4 x3 = xl[(size_t)c3 * 32 + lane];
        acc.x += v0 * x0.x; acc.y += v0 * x0.y; acc.z += v0 * x0.z; acc.w += v0 * x0.w;
        acc.x += v1 * x1.x; acc.y += v1 * x1.y; acc.z += v1 * x1.z; acc.w += v1 * x1.w;
        acc.x += v2 * x2.x; acc.y += v2 * x2.y; acc.z += v2 * x2.z; acc.w += v2 * x2.w;
        acc.x += v3 * x3.x; acc.y += v3 * x3.y; acc.z += v3 * x3.z; acc.w += v3 * x3.w;
    }
    for (; i < e; i++) {
        const int c0 = ecol[i];
        const float v0 = eval_[i];
        float4 x0 = xl[(size_t)c0 * 32 + lane];
        acc.x += v0 * x0.x; acc.y += v0 * x0.y; acc.z += v0 * x0.z; acc.w += v0 * x0.w;
    }
    ((float4*)agg)[((size_t)l * NNODES + row) * 32 + lane] = acc;
}

// ================= retention spmm on [L,N] weights (gather) =================
__global__ void __launch_bounds__(256) ret_gather(
    const int* __restrict__ rowstart,
    const int* __restrict__ ecol, const float* __restrict__ eval_,
    const float* __restrict__ src, float* __restrict__ dst)
{
    const int row = (blockIdx.x * blockDim.x + threadIdx.x) >> 5;
    const int lane = threadIdx.x & 31;
    if (row >= NNODES) return;
    const int s = rowstart[row];
    const int e = rowstart[row + 1];

    float a0 = 0.f, a1 = 0.f, a2 = 0.f, a3 = 0.f;
    for (int i = s + lane; i < e; i += 32) {
        const int c = ecol[i];
        const float v = DECAYF * eval_[i];
        a0 += v * src[c];
        a1 += v * src[NNODES + c];
        a2 += v * src[2 * NNODES + c];
        a3 += v * src[3 * NNODES + c];
    }
#pragma unroll
    for (int off = 16; off; off >>= 1) {
        a0 += __shfl_xor_sync(0xFFFFFFFFu, a0, off);
        a1 += __shfl_xor_sync(0xFFFFFFFFu, a1, off);
        a2 += __shfl_xor_sync(0xFFFFFFFFu, a2, off);
        a3 += __shfl_xor_sync(0xFFFFFFFFu, a3, off);
    }
    if (lane == 0) {
        dst[row]              = a0;
        dst[NNODES + row]     = a1;
        dst[2 * NNODES + row] = a2;
        dst[3 * NNODES + row] = a3;
    }
}

// ================= common MMA helpers =================
#define AST 132
#define BST 132
#define GEMM_SMEM ((64 * AST + 128 * BST) * 4)   // 101376 bytes

__device__ __forceinline__ void mma8(float* c, const unsigned* a, unsigned b0, unsigned b1)
{
    asm volatile(
        "mma.sync.aligned.m16n8k8.row.col.f32.tf32.tf32.f32 "
        "{%0,%1,%2,%3},{%4,%5,%6,%7},{%8,%9},{%0,%1,%2,%3};"
        : "+f"(c[0]), "+f"(c[1]), "+f"(c[2]), "+f"(c[3])
        : "r"(a[0]), "r"(a[1]), "r"(a[2]), "r"(a[3]), "r"(b0), "r"(b1));
}

#define LDSM4(r, addr) \
    asm volatile("ldmatrix.sync.aligned.m8n8.x4.shared.b16 {%0,%1,%2,%3}, [%4];" \
        : "=r"((r)[0]), "=r"((r)[1]), "=r"((r)[2]), "=r"((r)[3]) : "r"(addr))

__device__ __forceinline__ void fillA(unsigned* As, const float* A, int blockRow, int tid)
{
    const float4* Ag = (const float4*)(A + (size_t)blockRow * DDIM);
#pragma unroll
    for (int f = 0; f < 8; f++) {
        int i4 = tid + f * 256;
        float4 t = Ag[i4];
        int e = i4 * 4;
        *(uint4*)(As + (e >> 7) * AST + (e & 127)) =
            make_uint4(f2tf(t.x), f2tf(t.y), f2tf(t.z), f2tf(t.w));
    }
}

// B-tile fill: weights pre-converted to tf32 bits — raw uint4 copy
__device__ __forceinline__ void fillB(unsigned* Bs, const unsigned* Bt, int tid)
{
    const uint4* Bg = (const uint4*)Bt;
#pragma unroll
    for (int f = 0; f < 16; f++) {
        int i4 = tid + f * 256;
        uint4 t = Bg[i4];
        int e = i4 * 4;
        *(uint4*)(Bs + (e >> 7) * BST + (e & 127)) = t;
    }
}

__device__ __forceinline__ void mma_loop(float acc[8][4], unsigned aAddr, unsigned bAddr)
{
#pragma unroll
    for (int k8 = 0; k8 < 16; k8++) {
        const unsigned ko = k8 * 32;
        unsigned af[4], bf[4][4];
        LDSM4(af, aAddr + ko);
        LDSM4(bf[0], bAddr + ko);
        LDSM4(bf[1], bAddr + 16 * BST * 4 + ko);
        LDSM4(bf[2], bAddr + 32 * BST * 4 + ko);
        LDSM4(bf[3], bAddr + 48 * BST * 4 + ko);
#pragma unroll
        for (int nt = 0; nt < 8; nt++)
            mma8(acc[nt], af, bf[nt >> 1][(nt & 1) * 2], bf[nt >> 1][(nt & 1) * 2 + 1]);
    }
}

// LN(silu(.)) -> global store
__device__ __forceinline__ void ln_epilogue(
    const float* Cs, int blockRow, int wid, int lane,
    const float* bias, const float* addb,
    const float* lng, const float* lnb, float* C)
{
    float4 bias4 = make_float4(0.f, 0.f, 0.f, 0.f);
    if (bias) bias4 = ((const float4*)bias)[lane];
    const float4 g4 = ((const float4*)lng)[lane];
    const float4 b4 = ((const float4*)lnb)[lane];
#pragma unroll
    for (int i = 0; i < 8; i++) {
        const int r = wid * 8 + i;
        const size_t gr_ = (size_t)blockRow + r;
        float4 t = *(const float4*)(Cs + r * AST + lane * 4);
        t.x += bias4.x; t.y += bias4.y; t.z += bias4.z; t.w += bias4.w;
        if (addb) {
            float4 ad = ((const float4*)addb)[gr_ * 32 + lane];
            t.x += ad.x; t.y += ad.y; t.z += ad.z; t.w += ad.w;
        }
        float4 s;
        s.x = t.x / (1.f + expf(-t.x));
        s.y = t.y / (1.f + expf(-t.y));
        s.z = t.z / (1.f + expf(-t.z));
        s.w = t.w / (1.f + expf(-t.w));
        float sum = s.x + s.y + s.z + s.w;
        float sq  = s.x * s.x + s.y * s.y + s.z * s.z + s.w * s.w;
#pragma unroll
        for (int off = 16; off; off >>= 1) {
            sum += __shfl_xor_sync(0xFFFFFFFFu, sum, off);
            sq  += __shfl_xor_sync(0xFFFFFFFFu, sq,  off);
        }
        const float mean = sum * (1.f / 128.f);
        const float var  = sq * (1.f / 128.f) - mean * mean;
        const float rstd = rsqrtf(var + EPSF);
        float4 o;
        o.x = (s.x - mean) * rstd * g4.x + b4.x;
        o.y = (s.y - mean) * rstd * g4.y + b4.y;
        o.z = (s.z - mean) * rstd * g4.z + b4.z;
        o.w = (s.w - mean) * rstd * g4.w + b4.w;
        ((float4*)C)[gr_ * 32 + lane] = o;
    }
}

// LN(silu(.)) from CsB -> tf32 into As tile (for chained GEMM)
__device__ __forceinline__ void ln_to_As(
    const float* CsB, unsigned* As, int wid, int lane,
    const float* bias, const float* lng, const float* lnb)
{
    float4 bias4 = make_float4(0.f, 0.f, 0.f, 0.f);
    if (bias) bias4 = ((const float4*)bias)[lane];
    const float4 g4 = ((const float4*)lng)[lane];
    const float4 b4 = ((const float4*)lnb)[lane];
#pragma unroll
    for (int i = 0; i < 8; i++) {
        const int r = wid * 8 + i;
        float4 t = *(const float4*)(CsB + r * AST + lane * 4);
        t.x += bias4.x; t.y += bias4.y; t.z += bias4.z; t.w += bias4.w;
        float4 s;
        s.x = t.x / (1.f + expf(-t.x));
        s.y = t.y / (1.f + expf(-t.y));
        s.z = t.z / (1.f + expf(-t.z));
        s.w = t.w / (1.f + expf(-t.w));
        float sum = s.x + s.y + s.z + s.w;
        float sq  = s.x * s.x + s.y * s.y + s.z * s.z + s.w * s.w;
#pragma unroll
        for (int off = 16; off; off >>= 1) {
            sum += __shfl_xor_sync(0xFFFFFFFFu, sum, off);
            sq  += __shfl_xor_sync(0xFFFFFFFFu, sq,  off);
        }
        const float mean = sum * (1.f / 128.f);
        const float var  = sq * (1.f / 128.f) - mean * mean;
        const float rstd = rsqrtf(var + EPSF);
        float4 o;
        o.x = (s.x - mean) * rstd * g4.x + b4.x;
        o.y = (s.y - mean) * rstd * g4.y + b4.y;
        o.z = (s.z - mean) * rstd * g4.z + b4.z;
        o.w = (s.w - mean) * rstd * g4.w + b4.w;
        *(uint4*)(As + r * AST + lane * 4) =
            make_uint4(f2tf(o.x), f2tf(o.y), f2tf(o.z), f2tf(o.w));
    }
}

__device__ __forceinline__ void stage_acc(float* Cs, const float acc[8][4],
                                          int wr, int wc, int tg, int gr)
{
    const int r0 = wr * 16 + gr;
#pragma unroll
    for (int nt = 0; nt < 8; nt++) {
        const int c = wc * 64 + nt * 8 + 2 * tg;
        *(float2*)(Cs + r0 * AST + c)       = make_float2(acc[nt][0], acc[nt][1]);
        *(float2*)(Cs + (r0 + 8) * AST + c) = make_float2(acc[nt][2], acc[nt][3]);
    }
}

// ================= mega GEMM: full post-spmm chain, one kernel ===============
// v = x@Wv (scratch via global, same-CTA read-back)
// sage = LN(silu(x@sage_W + sage_b + agg@aggW))        [never leaves smem]
// att = LN(v * (w0+it1+it2))                           [computed in A-fill]
// h = LN(silu(sage@lin1_W0 + att@lin1_W1 + lin1_b))    [never leaves smem]
// out = LN(silu(h@lin2_W + lin2_b + x))
// bt layout: [0]=sage_W [1]=att_Wv [2]=sage_aggW [3,4]=lin1 [5]=lin2
__global__ void __launch_bounds__(256, 2) gemm_mega(
    const float* __restrict__ x, const float* __restrict__ agg,
    const unsigned* __restrict__ bt,
    const float* __restrict__ sage_b,
    const float* __restrict__ sage_g, const float* __restrict__ sage_lb,
    const float* __restrict__ w0, const float* __restrict__ it1,
    const float* __restrict__ it2,
    const float* __restrict__ attg, const float* __restrict__ attb,
    const float* __restrict__ lin1_b,
    const float* __restrict__ ln1g, const float* __restrict__ ln1b,
    const float* __restrict__ lin2_b,
    const float* __restrict__ ln2g, const float* __restrict__ ln2b,
    float* __restrict__ v, float* __restrict__ out)
{
    extern __shared__ unsigned smem_u[];
    unsigned* As = smem_u;
    unsigned* Bs = smem_u + 64 * AST;
    float* CsA = (float*)smem_u;
    float* CsB = (float*)(smem_u + 64 * AST);

    const int tid  = threadIdx.x;
    const int lane = tid & 31;
    const int wid  = tid >> 5;
    const int wr   = wid & 3;
    const int wc   = wid >> 2;
    const int tg   = lane & 3;
    const int gr   = lane >> 2;
    const int blockRow = blockIdx.x * 64;

    const unsigned sbase = (unsigned)__cvta_generic_to_shared(smem_u);
    const unsigned aAddr = sbase +
        ((wr * 16 + (lane & 15)) * AST + (lane >> 4) * 4) * 4u;
    const unsigned bAddr = sbase + 64u * AST * 4u +
        ((wc * 64 + (lane >> 4) * 8 + (lane & 7)) * BST + ((lane >> 3) & 1) * 4) * 4u;

    float acc[8][4];

    // ---- pass 1: v = x @ Wv -> global scratch (read back in att fill) ----
    fillA(As, x, blockRow, tid);
    fillB(Bs, bt + 1 * DDIM * DDIM, tid);
    __syncthreads();
#pragma unroll
    for (int i = 0; i < 8; i++)
#pragma unroll
        for (int j = 0; j < 4; j++) acc[i][j] = 0.f;
    mma_loop(acc, aAddr, bAddr);
    {
        const int r0 = blockRow + wr * 16 + gr;
#pragma unroll
        for (int nt = 0; nt < 8; nt++) {
            const int c = wc * 64 + nt * 8 + 2 * tg;
            ((float2*)v)[(size_t)r0 * 64 + (c >> 1)]       = make_float2(acc[nt][0], acc[nt][1]);
            ((float2*)v)[(size_t)(r0 + 8) * 64 + (c >> 1)] = make_float2(acc[nt][2], acc[nt][3]);
        }
    }
    __syncthreads();

    // ---- pass 2: acc = x @ sage_W (As still holds x) ----
    fillB(Bs, bt + 0 * DDIM * DDIM, tid);
    __syncthreads();
#pragma unroll
    for (int i = 0; i < 8; i++)
#pragma unroll
        for (int j = 0; j < 4; j++) acc[i][j] = 0.f;
    mma_loop(acc, aAddr, bAddr);
    __syncthreads();

    // ---- pass 3: acc += agg @ aggW ----
    fillA(As, agg, blockRow, tid);
    fillB(Bs, bt + 2 * DDIM * DDIM, tid);
    __syncthreads();
    mma_loop(acc, aAddr, bAddr);
    __syncthreads();

    // ---- sage = LN(silu(acc + sage_b)) -> tf32 directly into As ----
    stage_acc(CsB, acc, wr, wc, tg, gr);
    __syncthreads();
    ln_to_As(CsB, As, wid, lane, sage_b, sage_g, sage_lb);
    __syncthreads();

    // ---- lin1 chunk 0: acc = sage @ W0 ----
    fillB(Bs, bt + 3 * DDIM * DDIM, tid);
    __syncthreads();
#pragma unroll
    for (int i = 0; i < 8; i++)
#pragma unroll
        for (int j = 0; j < 4; j++) acc[i][j] = 0.f;
    mma_loop(acc, aAddr, bAddr);
    __syncthreads();

    // ---- lin1 chunk 1: att on the fly into As ----
    {
        const float4 ag4 = ((const float4*)attg)[lane];
        const float4 ab4 = ((const float4*)attb)[lane];
        const float4* Vg = (const float4*)(v + (size_t)blockRow * DDIM);
#pragma unroll
        for (int f = 0; f < 8; f++) {
            int i4 = tid + f * 256;
            int row = i4 >> 5;
            int g   = i4 & 31;
            size_t gr_ = (size_t)blockRow + row;
            float4 s = Vg[i4];
            const float w = w0[gr_] + it1[gr_] + it2[gr_];
            s.x *= w; s.y *= w; s.z *= w; s.w *= w;
            float sum = s.x + s.y + s.z + s.w;
            float sq  = s.x * s.x + s.y * s.y + s.z * s.z + s.w * s.w;
#pragma unroll
            for (int off = 16; off; off >>= 1) {
                sum += __shfl_xor_sync(0xFFFFFFFFu, sum, off);
                sq  += __shfl_xor_sync(0xFFFFFFFFu, sq,  off);
            }
            const float mean = sum * (1.f / 128.f);
            const float var  = sq * (1.f / 128.f) - mean * mean;
            const float rstd = rsqrtf(var + EPSF);
            float4 o;
            o.x = (s.x - mean) * rstd * ag4.x + ab4.x;
            o.y = (s.y - mean) * rstd * ag4.y + ab4.y;
            o.z = (s.z - mean) * rstd * ag4.z + ab4.z;
            o.w = (s.w - mean) * rstd * ag4.w + ab4.w;
            *(uint4*)(As + row * AST + g * 4) =
                make_uint4(f2tf(o.x), f2tf(o.y), f2tf(o.z), f2tf(o.w));
        }
    }
    fillB(Bs, bt + 4 * DDIM * DDIM, tid);
    __syncthreads();
    mma_loop(acc, aAddr, bAddr);
    __syncthreads();

    // ---- h = LN(silu(acc + lin1_b)) -> tf32 into As ----
    stage_acc(CsB, acc, wr, wc, tg, gr);
    __syncthreads();
    ln_to_As(CsB, As, wid, lane, lin1_b, ln1g, ln1b);
    __syncthreads();

    // ---- lin2: out = LN(silu(h@W2 + lin2_b + x)) ----
#pragma unroll
    for (int i = 0; i < 8; i++)
#pragma unroll
        for (int j = 0; j < 4; j++) acc[i][j] = 0.f;
    fillB(Bs, bt + 5 * DDIM * DDIM, tid);
    __syncthreads();
    mma_loop(acc, aAddr, bAddr);
    __syncthreads();

    stage_acc(CsA, acc, wr, wc, tg, gr);
    __syncthreads();
    ln_epilogue(CsA, blockRow, wid, lane, lin2_b, x, ln2g, ln2b, out);
}

// ---------------- k/q retention weights (fp32, exact) ----------------
__global__ void kq_kernel(const float* __restrict__ x,
                          const float* __restrict__ Wk, const float* __restrict__ Wq,
                          float* __restrict__ w0)
{
    __shared__ float4 sk4[KDIM * 32];
    __shared__ float4 sq4[KDIM * 32];
    float* sk = (float*)sk4;
    float* sqm = (float*)sq4;
    for (int idx = threadIdx.x; idx < DDIM * KDIM; idx += blockDim.x) {
        int k = idx >> 4, j = idx & 15;
        sk[j * DDIM + k] = Wk[idx];
        sqm[j * DDIM + k] = Wq[idx];
    }
    __syncthreads();

    const int lane = threadIdx.x & 31;
    int warp = (blockIdx.x * blockDim.x + threadIdx.x) >> 5;
    const int nwarps = (gridDim.x * blockDim.x) >> 5;

    for (size_t r = warp; r < (size_t)MROWS; r += nwarps) {
        const float4 xv = ((const float4*)x)[r * 32 + lane];
        float pk[KDIM], pq[KDIM];
#pragma unroll
        for (int j = 0; j < KDIM; j++) {
            float4 wk = sk4[j * 32 + lane];
            float4 wq = sq4[j * 32 + lane];
            pk[j] = xv.x * wk.x + xv.y * wk.y + xv.z * wk.z + xv.w * wk.w;
            pq[j] = xv.x * wq.x + xv.y * wq.y + xv.z * wq.z + xv.w * wq.w;
        }
#pragma unroll
        for (int off = 16; off; off >>= 1) {
#pragma unroll
            for (int j = 0; j < KDIM; j++) {
                pk[j] += __shfl_xor_sync(0xFFFFFFFFu, pk[j], off);
                pq[j] += __shfl_xor_sync(0xFFFFFFFFu, pq[j], off);
            }
        }
        if (lane == 0) {
            float s = 0.f;
#pragma unroll
            for (int j = 0; j < KDIM; j++) s += pk[j] * pq[j];
            w0[r] = s * (1.f / (float)KDIM);
        }
    }
}

// ---------------- host ----------------
extern "C" void kernel_launch(void* const* d_in, const int* in_sizes, int n_in,
                              void* d_out, int out_size)
{
    const float* x          = (const float*)d_in[0];
    const int*   ei         = (const int*)  d_in[1];
    const float* ev         = (const float*)d_in[2];
    const float* sage_W     = (const float*)d_in[3];
    const float* sage_b     = (const float*)d_in[4];
    const float* sage_aggW  = (const float*)d_in[5];
    const float* sage_ln_g  = (const float*)d_in[6];
    const float* sage_ln_b  = (const float*)d_in[7];
    const float* att_Wk     = (const float*)d_in[8];
    const float* att_Wq     = (const float*)d_in[9];
    const float* att_Wv     = (const float*)d_in[10];
    const float* att_ln_g   = (const float*)d_in[11];
    const float* att_ln_b   = (const float*)d_in[12];
    const float* lin1_W     = (const float*)d_in[13];
    const float* lin1_b     = (const float*)d_in[14];
    const float* lin2_W     = (const float*)d_in[15];
    const float* lin2_b     = (const float*)d_in[16];
    const float* ln1_g      = (const float*)d_in[17];
    const float* ln1_b      = (const float*)d_in[18];
    const float* ln2_g      = (const float*)d_in[19];
    const float* ln2_b      = (const float*)d_in[20];
    float* out = (float*)d_out;

    float *v, *agg, *w0, *it1, *it2;
    unsigned *bt;
    cudaGetSymbolAddress((void**)&v,    g_v);
    cudaGetSymbolAddress((void**)&agg,  g_agg);
    cudaGetSymbolAddress((void**)&w0,   g_w0);
    cudaGetSymbolAddress((void**)&it1,  g_it1);
    cudaGetSymbolAddress((void**)&it2,  g_it2);
    cudaGetSymbolAddress((void**)&bt,   g_bt);

    int *cnt2, *rowstart, *ecol;
    float *eval_;
    cudaGetSymbolAddress((void**)&cnt2,     g_cnt2);
    cudaGetSymbolAddress((void**)&rowstart, g_rowstart);
    cudaGetSymbolAddress((void**)&ecol,     g_ecol);
    cudaGetSymbolAddress((void**)&eval_,    g_eval);
    int* cnt = cnt2;
    int* cur = cnt2 + NNODES;

    cudaFuncSetAttribute(gemm_mega, cudaFuncAttributeMaxDynamicSharedMemorySize, GEMM_SMEM);

    const int gemmGrid = MROWS / 64; // 3125

    // launch 1: prep (weight transpose+tf32 convert AND clear cnt/cur)
    SixPtr sp;
    sp.p[0] = sage_W; sp.p[1] = att_Wv; sp.p[2] = sage_aggW;
    sp.p[3] = lin1_W; sp.p[4] = lin1_W + DDIM * DDIM; sp.p[5] = lin2_W;
    prep_kernel<<<PREP_TRANS_BLOCKS + PREP_CLEAR_BLOCKS, 256>>>(sp, bt, cnt2);

    // launch 2-4: CSR build
    hist_kernel<<<(EEDGES + 255) / 256, 256>>>(ei, cnt);
    scan_kernel<<<1, 1024>>>(cnt, rowstart);
    scatter_kernel<<<(EEDGES + 255) / 256, 256>>>(ei, ev, rowstart, cur, ecol, eval_);

    // launch 5: merged spmm, blockIdx.y = l (slice-major order)
    {
        dim3 grid((NNODES * 32 + 255) / 256, LDIM);
        spmm_all<<<grid, 256>>>(rowstart, ecol, eval_, x, agg);
    }

    // launch 6-8: retention weights
    kq_kernel<<<1480, 256>>>(x, att_Wk, att_Wq, w0);
    ret_gather<<<(NNODES * 32 + 255) / 256, 256>>>(rowstart, ecol, eval_, w0, it1);
    ret_gather<<<(NNODES * 32 + 255) / 256, 256>>>(rowstart, ecol, eval_, it1, it2);

    // launch 9: the whole GEMM chain in one kernel
    gemm_mega<<<gemmGrid, 256, GEMM_SMEM>>>(x, agg, bt,
                                            sage_b, sage_ln_g, sage_ln_b,
                                            w0, it1, it2,
                                            att_ln_g, att_ln_b,
                                            lin1_b, ln1_g, ln1_b,
                                            lin2_b, ln2_g, ln2_b,
                                            v, out);
}